// round 14
// baseline (speedup 1.0000x reference)
#include <cuda_runtime.h>
#include <cstdint>
#include <math.h>

// Problem constants (fixed by setup_inputs)
#define Bb   4
#define Kk   256
#define BQ   1024      // B*K
#define Cc   256
#define Ll   100000
#define LB   (Ll / Bb) // 25000 voxels per batch
#define Nn   64
#define Hh   128
#define CAP  256
#define QPB  8
#define SCAT 384       // concat width: 256 | 128

// ---------------- device scratch ----------------
__device__ int    g_nbr_idx[BQ * Nn];
__device__ int    g_nbr_cnt[BQ];
__device__ float  g_Q[BQ * Cc];
__device__ float  g_QKcat[BQ * SCAT];    // [qk | qk2]
__device__ float  g_Scat[BQ * SCAT];     // [Svf | Sh]
__device__ int    g_anyv[BQ];
__device__ float  g_Wk2[Cc * Hh];        // wk @ pos_w2
__device__ float  g_X2[Cc * Hh];         // wv @ pos_w2
__device__ float  g_Wvocat[Cc * SCAT];   // [wo@wv | wo@(wv@pos_w2)]
__device__ float  g_cvec[Cc];

// ---------------- scheduling state (reset each launch) ----------------
__device__ int g_ticket;
__device__ int c_search, c_Q, c_wk2, c_x2, c_wvo, c_wvo2, c_cvec, c_qk, c_qk2, c_attn;

// task layout
#define T_SEARCH0 0
#define T_Q0      128
#define T_WK20    192
#define T_X20     200
#define T_WVO0    208
#define T_WVO20   224
#define T_CVEC0   232
#define T_QK0     240
#define T_QK20    304
#define T_ATTN0   336
#define T_TAIL0   1360
#define T_TOTAL   1424

#define SMEM_BYTES 34816   // max over gemm(34816), search(~16.5K), attn(~6K)

__global__ void k_reset() {
    g_ticket = 0;
    c_search = 0; c_Q = 0; c_wk2 = 0; c_x2 = 0; c_wvo = 0;
    c_wvo2 = 0; c_cvec = 0; c_qk = 0; c_qk2 = 0; c_attn = 0;
}

// ---- sync helpers ----
__device__ __forceinline__ void wait_ctr(int* ctr, int target) {
    if (threadIdx.x == 0) {
        while (atomicAdd(ctr, 0) < target) __nanosleep(200);
    }
    __syncthreads();
    __threadfence();
}
__device__ __forceinline__ void signal_ctr(int* ctr) {
    __syncthreads();
    __threadfence();
    if (threadIdx.x == 0) atomicAdd(ctr, 1);
}

// ---- voxel center, reference-exact rounding ----
__device__ __forceinline__ float3 voxel_center(int4 r) {
    float3 v;
    v.x = __fadd_rn(__fmul_rn(__fadd_rn((float)r.w, 0.5f), 0.2f), -25.6f);
    v.y = __fadd_rn(__fmul_rn(__fadd_rn((float)r.z, 0.5f), 0.2f), -25.6f);
    v.z = __fadd_rn(__fmul_rn(__fadd_rn((float)r.y, 0.5f), 0.2f), -2.0f);
    return v;
}

// ---------------- task: radius search + exact top-64 (bit-exact d2) --------
__device__ void task_search(int blk, const float* __restrict__ q_xyz,
                            const int* __restrict__ sp_idx, char* sm) {
    unsigned long long (*cand)[CAP] = (unsigned long long (*)[CAP])sm;
    int* cnt = (int*)(sm + QPB * CAP * 8);
    int tid = threadIdx.x;
    int q0 = blk * QPB;
    int qb = q0 / Kk;
    if (tid < QPB) cnt[tid] = 0;
    __syncthreads();

    float qx[QPB], qy[QPB], qz[QPB], qn[QPB];
#pragma unroll
    for (int j = 0; j < QPB; j++) {
        int q = q0 + j;
        qx[j] = q_xyz[q * 3 + 0];
        qy[j] = q_xyz[q * 3 + 1];
        qz[j] = q_xyz[q * 3 + 2];
        qn[j] = __fadd_rn(__fadd_rn(__fmul_rn(qx[j], qx[j]),
                                    __fmul_rn(qy[j], qy[j])),
                          __fmul_rn(qz[j], qz[j]));
    }

    const int4* sp4 = (const int4*)sp_idx;
    int base = qb * LB;
    for (int l = base + tid; l < base + LB; l += 256) {
        float3 v = voxel_center(sp4[l]);
        float vn = __fadd_rn(__fadd_rn(__fmul_rn(v.x, v.x), __fmul_rn(v.y, v.y)),
                             __fmul_rn(v.z, v.z));
#pragma unroll
        for (int j = 0; j < QPB; j++) {
            float dot = __fmaf_rn(qz[j], v.z,
                        __fmaf_rn(qy[j], v.y, __fmul_rn(qx[j], v.x)));
            float d2 = __fsub_rn(__fadd_rn(qn[j], vn), __fmul_rn(2.0f, dot));
            if (d2 <= 2.2501f) {
                float dist = __fsqrt_rn(fmaxf(d2, 0.0f));
                if (dist <= 1.5f) {
                    int pos = atomicAdd(&cnt[j], 1);
                    if (pos < CAP)
                        cand[j][pos] =
                            (((unsigned long long)__float_as_uint(dist)) << 32) |
                            (unsigned int)l;
                }
            }
        }
    }
    __syncthreads();

    for (int j = 0; j < QPB; j++) {
        int c = min(cnt[j], CAP);
        int q = q0 + j;
        if (c > 1) {
            int P = 1;
            while (P < c) P <<= 1;
            for (int i = tid; i < P; i += 256)
                if (i >= c) cand[j][i] = ~0ULL;
            __syncthreads();
            // bitonic sort by (dist_bits, idx): matches top_k tie-break
            for (int k = 2; k <= P; k <<= 1) {
                for (int jj = k >> 1; jj > 0; jj >>= 1) {
                    for (int i = tid; i < P; i += 256) {
                        int l2 = i ^ jj;
                        if (l2 > i) {
                            bool up = ((i & k) == 0);
                            unsigned long long a = cand[j][i];
                            unsigned long long b = cand[j][l2];
                            bool sw = up ? (a > b) : (a < b);
                            if (sw) { cand[j][i] = b; cand[j][l2] = a; }
                        }
                    }
                    __syncthreads();
                }
            }
        }
        int nv = min(c, Nn);
        if (tid < Nn)
            g_nbr_idx[q * Nn + tid] =
                (tid < nv) ? (int)(cand[j][tid] & 0xffffffffu) : -1;
        if (tid == 0) g_nbr_cnt[q] = nv;
        __syncthreads();
    }
}

// ---------------- task: deep-K GEMM tile (64x64, BK=32, double-buffered) ---
template <bool AT, bool WT>
__device__ void gemm_task(int bx, int by,
                          const float* __restrict__ A, const float* __restrict__ W,
                          const float* __restrict__ bias, const int* __restrict__ rowmask,
                          float* __restrict__ C, int M, int N, int K,
                          int lda, int ldw, int ldc, char* sm) {
    float (*As)[32][68] = (float (*)[32][68])sm;
    float (*Ws)[32][68] = (float (*)[32][68])(sm + 17408);
    int m0 = by * 64, n0 = bx * 64;
    int tid = threadIdx.x;
    int tx = tid & 15, ty = tid >> 4;

    int ar0, ac;
    if (AT) { ar0 = tid >> 4; ac = tid & 15; }
    else    { ar0 = tid >> 3; ac = tid & 7;  }
    int wr0, wc;
    if (WT) { wr0 = tid >> 3; wc = tid & 7;  }
    else    { wr0 = tid >> 4; wc = tid & 15; }

    float acc[4][4];
#pragma unroll
    for (int i = 0; i < 4; i++)
#pragma unroll
        for (int j = 0; j < 4; j++) acc[i][j] = 0.f;

    auto fetchA = [&](int k0, int h) -> float4 {
        if (AT) return *(const float4*)&A[(size_t)(k0 + ar0 + h * 16) * lda + m0 + ac * 4];
        else    return *(const float4*)&A[(size_t)(m0 + ar0 + h * 32) * lda + k0 + ac * 4];
    };
    auto fetchW = [&](int k0, int h) -> float4 {
        if (WT) return *(const float4*)&W[(size_t)(n0 + wr0 + h * 32) * ldw + k0 + wc * 4];
        else    return *(const float4*)&W[(size_t)(k0 + wr0 + h * 16) * ldw + n0 + wc * 4];
    };
    auto storeA = [&](int b, float4 v, int h) {
        float r[4] = {v.x, v.y, v.z, v.w};
#pragma unroll
        for (int j = 0; j < 4; j++) {
            if (AT) As[b][ar0 + h * 16][ac * 4 + j] = r[j];
            else    As[b][ac * 4 + j][ar0 + h * 32] = r[j];
        }
    };
    auto storeW = [&](int b, float4 v, int h) {
        float r[4] = {v.x, v.y, v.z, v.w};
#pragma unroll
        for (int j = 0; j < 4; j++) {
            if (WT) Ws[b][wc * 4 + j][wr0 + h * 32] = r[j];
            else    Ws[b][wr0 + h * 16][wc * 4 + j] = r[j];
        }
    };

    int nk = K >> 5;
    float4 ra0 = fetchA(0, 0), ra1 = fetchA(0, 1);
    float4 rw0 = fetchW(0, 0), rw1 = fetchW(0, 1);
    storeA(0, ra0, 0); storeA(0, ra1, 1);
    storeW(0, rw0, 0); storeW(0, rw1, 1);
    __syncthreads();

    int buf = 0;
    for (int it = 0; it < nk; ++it) {
        bool more = (it + 1) < nk;
        if (more) {
            int k0 = (it + 1) << 5;
            ra0 = fetchA(k0, 0); ra1 = fetchA(k0, 1);
            rw0 = fetchW(k0, 0); rw1 = fetchW(k0, 1);
        }
#pragma unroll
        for (int kk = 0; kk < 32; kk++) {
            float a[4], b[4];
#pragma unroll
            for (int i = 0; i < 4; i++) a[i] = As[buf][kk][ty * 4 + i];
#pragma unroll
            for (int j = 0; j < 4; j++) b[j] = Ws[buf][kk][tx * 4 + j];
#pragma unroll
            for (int i = 0; i < 4; i++)
#pragma unroll
                for (int j = 0; j < 4; j++) acc[i][j] += a[i] * b[j];
        }
        if (more) {
            storeA(buf ^ 1, ra0, 0); storeA(buf ^ 1, ra1, 1);
            storeW(buf ^ 1, rw0, 0); storeW(buf ^ 1, rw1, 1);
        }
        __syncthreads();
        buf ^= 1;
    }

#pragma unroll
    for (int i = 0; i < 4; i++) {
        int m = m0 + ty * 4 + i;
        bool zero = rowmask && rowmask[m] == 0;
#pragma unroll
        for (int j = 0; j < 4; j++) {
            int n = n0 + tx * 4 + j;
            float v = acc[i][j];
            if (bias) v += bias[n];
            if (zero) v = 0.f;
            C[(size_t)m * ldc + n] = v;
        }
    }
}

// ---------------- task: cvec (32 outputs per task) -------------------------
__device__ void task_cvec(int id, const float* __restrict__ b2,
                          const float* __restrict__ bv,
                          const float* __restrict__ wo,
                          const float* __restrict__ bo, char* sm) {
    float* red = (float*)sm;
    int tid = threadIdx.x;
    for (int k = 0; k < 32; k++) {
        int o = id * 32 + k;
        red[tid] = g_Wvocat[o * SCAT + tid] * b2[tid] + wo[o * Cc + tid] * bv[tid];
        __syncthreads();
        for (int s = 128; s > 0; s >>= 1) {
            if (tid < s) red[tid] += red[tid + s];
            __syncthreads();
        }
        if (tid == 0) g_cvec[o] = red[0] + bo[o];
        __syncthreads();
    }
}

// ---------------- task: streaming attention (per query) --------------------
struct SmemK4 {
    float  qk[Cc];
    float  qk2[Hh];
    float4 relin[Nn];
    int    idxs[Nn];
    float  scores[Nn];
    float  attn[Nn];
    float  w1s[Hh][4];
    float  b1s[Hh];
};

__device__ void task_attn(int q, const float* __restrict__ q_xyz,
                          const float* __restrict__ sp_feat,
                          const int* __restrict__ sp_idx,
                          const float* __restrict__ pos_w1,
                          const float* __restrict__ pos_b1, char* sm) {
    SmemK4* S = (SmemK4*)sm;
    int tid = threadIdx.x;
    int cnt = g_nbr_cnt[q];

    if (cnt == 0) {
        g_Scat[q * SCAT + tid] = 0.f;
        if (tid < Hh) g_Scat[q * SCAT + Cc + tid] = 0.f;
        if (tid == 0) g_anyv[q] = 0;
        return;
    }
    if (tid == 0) g_anyv[q] = 1;

    S->qk[tid] = g_QKcat[q * SCAT + tid];
    if (tid < Hh) {
        S->qk2[tid] = g_QKcat[q * SCAT + Cc + tid];
        S->b1s[tid] = pos_b1[tid];
        float4 w = ((const float4*)pos_w1)[tid];
        S->w1s[tid][0] = w.x; S->w1s[tid][1] = w.y;
        S->w1s[tid][2] = w.z; S->w1s[tid][3] = w.w;
    }
    if (tid < cnt) S->idxs[tid] = g_nbr_idx[q * Nn + tid];
    float qxv = q_xyz[q * 3 + 0], qyv = q_xyz[q * 3 + 1], qzv = q_xyz[q * 3 + 2];
    __syncthreads();

    if (tid < cnt) {
        float3 v = voxel_center(((const int4*)sp_idx)[S->idxs[tid]]);
        float rx = v.x - qxv, ry = v.y - qyv, rz = v.z - qzv;
        float d = sqrtf(rx * rx + ry * ry + rz * rz);
        S->relin[tid] = make_float4(rx, ry, rz, d);
    }
    __syncthreads();

    // scores
    int warp = tid >> 5, lane = tid & 31;
    for (int n = warp; n < cnt; n += 8) {
        const float* __restrict__ vrow = sp_feat + (size_t)S->idxs[n] * Cc;
        float4 r = S->relin[n];
        float acc = 0.f;
#pragma unroll
        for (int jj = 0; jj < 8; jj++)
            acc += S->qk[lane + 32 * jj] * __ldg(&vrow[lane + 32 * jj]);
#pragma unroll
        for (int jj = 0; jj < 4; jj++) {
            int hh = lane + 32 * jj;
            float hv = fmaxf(S->b1s[hh] + S->w1s[hh][0] * r.x +
                             S->w1s[hh][1] * r.y + S->w1s[hh][2] * r.z +
                             S->w1s[hh][3] * r.w, 0.f);
            acc += S->qk2[hh] * hv;
        }
        for (int o = 16; o > 0; o >>= 1)
            acc += __shfl_down_sync(0xffffffffu, acc, o);
        if (lane == 0) S->scores[n] = acc * 0.0625f;
    }
    __syncthreads();

    // softmax (warp 0)
    if (warp == 0) {
        float s0 = (lane < cnt) ? S->scores[lane] : -1e30f;
        float s1 = (lane + 32 < cnt) ? S->scores[lane + 32] : -1e30f;
        float m = fmaxf(s0, s1);
        for (int o = 16; o > 0; o >>= 1)
            m = fmaxf(m, __shfl_xor_sync(0xffffffffu, m, o));
        float p0 = (lane < cnt) ? expf(s0 - m) : 0.f;
        float p1 = (lane + 32 < cnt) ? expf(s1 - m) : 0.f;
        float sum = p0 + p1;
        for (int o = 16; o > 0; o >>= 1)
            sum += __shfl_xor_sync(0xffffffffu, sum, o);
        float inv = 1.f / sum;
        if (lane < cnt) S->attn[lane] = p0 * inv;
        if (lane + 32 < cnt) S->attn[lane + 32] = p1 * inv;
    }
    __syncthreads();

    // weighted sums
    float accv = 0.f, acch = 0.f;
    float w0 = 0.f, w1 = 0.f, w2 = 0.f, w3 = 0.f, b1 = 0.f;
    if (tid < Hh) {
        w0 = S->w1s[tid][0]; w1 = S->w1s[tid][1];
        w2 = S->w1s[tid][2]; w3 = S->w1s[tid][3];
        b1 = S->b1s[tid];
    }
#pragma unroll 4
    for (int n = 0; n < cnt; n++) {
        float a = S->attn[n];
        accv += a * __ldg(&sp_feat[(size_t)S->idxs[n] * Cc + tid]);
        if (tid < Hh) {
            float4 r = S->relin[n];
            float hv = fmaxf(b1 + w0 * r.x + w1 * r.y + w2 * r.z + w3 * r.w, 0.f);
            acch += a * hv;
        }
    }
    g_Scat[q * SCAT + tid] = accv;
    if (tid < Hh) g_Scat[q * SCAT + Cc + tid] = acch;
}

// ---------------- the megakernel ----------------
extern __shared__ char s_dyn[];

__global__ __launch_bounds__(256, 3)
void mega(const float* __restrict__ q_feat, const float* __restrict__ q_xyz,
          const float* __restrict__ sp_feat, const int* __restrict__ sp_idx,
          const float* __restrict__ pos_w1, const float* __restrict__ pos_b1,
          const float* __restrict__ pos_w2, const float* __restrict__ pos_b2,
          const float* __restrict__ wq, const float* __restrict__ bq,
          const float* __restrict__ wk, const float* __restrict__ wv,
          const float* __restrict__ bv, const float* __restrict__ wo,
          const float* __restrict__ bo, float* __restrict__ out) {
    __shared__ int s_ticket;
    char* sm = s_dyn;

    while (true) {
        __syncthreads();   // quiesce smem from previous task
        if (threadIdx.x == 0) s_ticket = atomicAdd(&g_ticket, 1);
        __syncthreads();
        int t = s_ticket;
        if (t >= T_TOTAL) return;

        if (t < T_Q0) {                       // search
            task_search(t, q_xyz, sp_idx, sm);
            signal_ctr(&c_search);
        } else if (t < T_WK20) {              // Q = q_feat@wq^T + bq
            int id = t - T_Q0;
            gemm_task<false, true>(id & 3, id >> 2, q_feat, wq, bq, nullptr,
                                   g_Q, BQ, Cc, Cc, Cc, Cc, Cc, sm);
            signal_ctr(&c_Q);
        } else if (t < T_X20) {               // Wk2 = wk@pos_w2
            int id = t - T_WK20;
            gemm_task<false, false>(id & 1, id >> 1, wk, pos_w2, nullptr, nullptr,
                                    g_Wk2, Cc, Hh, Cc, Cc, Hh, Hh, sm);
            signal_ctr(&c_wk2);
        } else if (t < T_WVO0) {              // X2 = wv@pos_w2
            int id = t - T_X20;
            gemm_task<false, false>(id & 1, id >> 1, wv, pos_w2, nullptr, nullptr,
                                    g_X2, Cc, Hh, Cc, Cc, Hh, Hh, sm);
            signal_ctr(&c_x2);
        } else if (t < T_WVO20) {             // Wvocat[:,0:256] = wo@wv
            int id = t - T_WVO0;
            gemm_task<false, false>(id & 3, id >> 2, wo, wv, nullptr, nullptr,
                                    g_Wvocat, Cc, Cc, Cc, Cc, Cc, SCAT, sm);
            signal_ctr(&c_wvo);
        } else if (t < T_CVEC0) {             // Wvocat[:,256:384] = wo@X2
            int id = t - T_WVO20;
            wait_ctr(&c_x2, 8);
            gemm_task<false, false>(id & 1, id >> 1, wo, g_X2, nullptr, nullptr,
                                    g_Wvocat + Cc, Cc, Hh, Cc, Cc, Hh, SCAT, sm);
            signal_ctr(&c_wvo2);
        } else if (t < T_QK0) {               // cvec
            int id = t - T_CVEC0;
            wait_ctr(&c_wvo, 16);
            task_cvec(id, pos_b2, bv, wo, bo, sm);
            signal_ctr(&c_cvec);
        } else if (t < T_QK20) {              // QKcat[:,0:256] = Q@wk
            int id = t - T_QK0;
            wait_ctr(&c_Q, 64);
            gemm_task<false, false>(id & 3, id >> 2, g_Q, wk, nullptr, nullptr,
                                    g_QKcat, BQ, Cc, Cc, Cc, Cc, SCAT, sm);
            signal_ctr(&c_qk);
        } else if (t < T_ATTN0) {             // QKcat[:,256:384] = Q@Wk2
            int id = t - T_QK20;
            wait_ctr(&c_Q, 64);
            wait_ctr(&c_wk2, 8);
            gemm_task<false, false>(id & 1, id >> 1, g_Q, g_Wk2, nullptr, nullptr,
                                    g_QKcat + Cc, BQ, Hh, Cc, Cc, Hh, SCAT, sm);
            signal_ctr(&c_qk2);
        } else if (t < T_TAIL0) {             // attention per query
            int q = t - T_ATTN0;
            wait_ctr(&c_search, 128);
            wait_ctr(&c_qk, 64);
            wait_ctr(&c_qk2, 32);
            task_attn(q, q_xyz, sp_feat, sp_idx, pos_w1, pos_b1, sm);
            signal_ctr(&c_attn);
        } else {                              // tail: out = Scat@Wvocat^T + cvec
            int id = t - T_TAIL0;
            wait_ctr(&c_attn, BQ);
            wait_ctr(&c_wvo2, 8);
            wait_ctr(&c_cvec, 8);
            gemm_task<false, true>(id & 3, id >> 2, g_Scat, g_Wvocat, g_cvec,
                                   g_anyv, out, BQ, Cc, SCAT, SCAT, SCAT, Cc, sm);
        }
    }
}

// ---------------- launch ----------------
extern "C" void kernel_launch(void* const* d_in, const int* in_sizes, int n_in,
                              void* d_out, int out_size) {
    const float* q_feat  = (const float*)d_in[0];
    const float* q_xyz   = (const float*)d_in[1];
    const float* sp_feat = (const float*)d_in[2];
    const int*   sp_idx  = (const int*)d_in[3];
    const float* pos_w1  = (const float*)d_in[4];
    const float* pos_b1  = (const float*)d_in[5];
    const float* pos_w2  = (const float*)d_in[6];
    const float* pos_b2  = (const float*)d_in[7];
    const float* wq      = (const float*)d_in[8];
    const float* bq      = (const float*)d_in[9];
    const float* wk      = (const float*)d_in[10];
    const float* bk      = (const float*)d_in[11];
    const float* wv      = (const float*)d_in[12];
    const float* bv      = (const float*)d_in[13];
    const float* wo      = (const float*)d_in[14];
    const float* bo      = (const float*)d_in[15];
    float* out = (float*)d_out;
    (void)bk;   // score bias is softmax-invariant

    k_reset<<<1, 1>>>();
    mega<<<444, 256, SMEM_BYTES>>>(q_feat, q_xyz, sp_feat, sp_idx,
                                   pos_w1, pos_b1, pos_w2, pos_b2,
                                   wq, bq, wk, wv, bv, wo, bo, out);
}